// round 3
// baseline (speedup 1.0000x reference)
#include <cuda_runtime.h>
#include <cstdint>

// Problem constants (fixed by the dataset)
#define B_    8
#define C_    64
#define H_    128
#define W_    128
#define HW_   (H_*W_)
#define COUT_ 64
#define K2_   9

// Pre-transposed weights: [k][c][o]  (9*64*64 floats)
__device__ float g_wT[K2_ * C_ * COUT_];

// ---------------------------------------------------------------------------
// Tiny pre-kernel: transpose weight [o][c][kh][kw] -> g_wT[k][c][o]
// so the per-k smem staging in the main kernel is fully coalesced.
// ---------------------------------------------------------------------------
__global__ void wtrans_kernel(const float* __restrict__ w) {
    int e = blockIdx.x * 256 + threadIdx.x;      // e = (o*64 + c)*9 + k
    if (e < K2_ * C_ * COUT_) {
        int k  = e % 9;
        int oc = e / 9;
        int c  = oc % C_;
        int o  = oc / C_;
        g_wT[(k * C_ + c) * COUT_ + o] = w[e];
    }
}

// packed f32x2 fma helpers
__device__ __forceinline__ unsigned long long pack2(float v) {
    unsigned long long r;
    asm("mov.b64 %0, {%1, %1};" : "=l"(r) : "f"(v));
    return r;
}
__device__ __forceinline__ void ffma2(unsigned long long& d,
                                      unsigned long long a,
                                      unsigned long long b) {
    asm("fma.rn.f32x2 %0, %1, %2, %0;" : "+l"(d) : "l"(a), "l"(b));
}
__device__ __forceinline__ float2 unpack2(unsigned long long v) {
    float2 r;
    asm("mov.b64 {%0, %1}, %2;" : "=f"(r.x), "=f"(r.y) : "l"(v));
    return r;
}

// ---------------------------------------------------------------------------
// Main fused kernel.
// One block = one (b, h) output row: 128 px * 64 Cout.
// blockDim = 256. Thread GEMM tile: 8 Cout x 4 px (16 f32x2 accumulators).
// ---------------------------------------------------------------------------
__global__ void __launch_bounds__(256)
dcn_kernel(const float* __restrict__ x,
           const float* __restrict__ offset,
           const float* __restrict__ mask,
           const float* __restrict__ bias,
           float* __restrict__ out) {
    extern __shared__ float sm[];
    float* cols = sm;                        // [64][128]   32 KB
    float* ws   = sm + C_ * 128;             // [c][o]      16 KB
    int4*   offs = (int4*)(sm + C_ * 128 + C_ * COUT_);   // [128] tap offsets
    float4* wts  = (float4*)(offs + 128);                 // [128] tap weights

    const int t = threadIdx.x;
    const int b = blockIdx.x >> 7;
    const int h = blockIdx.x & 127;

    const float* xb = x + b * C_ * HW_;

    // GEMM tile coords
    const int px0 = (t & 31) * 4;
    const int o0  = (t >> 5) * 8;

    // sampling coords
    const int spx = t & 127;
    const int c0  = (t >> 7) * 32;

    unsigned long long acc[16];
#pragma unroll
    for (int i = 0; i < 16; i++) acc[i] = 0ULL;

    for (int k = 0; k < 9; k++) {
        __syncthreads();   // previous-iteration readers done with cols/ws

        if (t < 128) {
            // ---- bilinear params for this k, one px per thread ----
            const int w = t;
            const int ky = k / 3;
            const int kx = k - ky * 3;
            float dx = offset[(((b * 18) + 2 * k    ) * 128 + h) * 128 + w];
            float dy = offset[(((b * 18) + 2 * k + 1) * 128 + h) * 128 + w];
            float m  = mask  [(((b * 9)  + k        ) * 128 + h) * 128 + w];
            float py  = (float)(h - 1 + ky) + dy;
            float pxf = (float)(w - 1 + kx) + dx;
            float y0 = floorf(py), x0f = floorf(pxf);
            float ly = py - y0,  lx = pxf - x0f;
            float hy = 1.0f - ly, hx = 1.0f - lx;
            int iy0 = (int)y0, ix0 = (int)x0f;
            int iy1 = iy0 + 1, ix1 = ix0 + 1;
            float vy0 = (iy0 >= 0 && iy0 < H_) ? 1.0f : 0.0f;
            float vy1 = (iy1 >= 0 && iy1 < H_) ? 1.0f : 0.0f;
            float vx0 = (ix0 >= 0 && ix0 < W_) ? 1.0f : 0.0f;
            float vx1 = (ix1 >= 0 && ix1 < W_) ? 1.0f : 0.0f;
            int iy0c = min(max(iy0, 0), H_ - 1);
            int iy1c = min(max(iy1, 0), H_ - 1);
            int ix0c = min(max(ix0, 0), W_ - 1);
            int ix1c = min(max(ix1, 0), W_ - 1);
            offs[w] = make_int4(iy0c * W_ + ix0c, iy0c * W_ + ix1c,
                                iy1c * W_ + ix0c, iy1c * W_ + ix1c);
            wts[w] = make_float4(hy * hx * m * vy0 * vx0,
                                 hy * lx * m * vy0 * vx1,
                                 ly * hx * m * vy1 * vx0,
                                 ly * lx * m * vy1 * vx1);
        } else {
            // ---- stage transposed weight slice [c][o] for this k ----
            const float* wk = g_wT + k * (C_ * COUT_);
            for (int e = t - 128; e < C_ * COUT_; e += 128)
                ws[e] = wk[e];
        }
        __syncthreads();

        // ---- build cols[c][px]: bilinear gather * (mask-folded weights) ----
        {
            int4   o4 = offs[spx];
            float4 w4 = wts[spx];
            const float* pc = xb + c0 * HW_;
#pragma unroll 4
            for (int i = 0; i < 32; i++) {
                float v = w4.x * __ldg(pc + o4.x) + w4.y * __ldg(pc + o4.y)
                        + w4.z * __ldg(pc + o4.z) + w4.w * __ldg(pc + o4.w);
                cols[(c0 + i) * 128 + spx] = v;
                pc += HW_;
            }
        }
        __syncthreads();

        // ---- GEMM: acc[8 o][4 px] += ws[c][o] * cols[c][px]  (f32x2) ----
#pragma unroll 8
        for (int c = 0; c < C_; c++) {
            ulonglong2 cv = *(const ulonglong2*)&cols[c * 128 + px0];
            float4 wa = *(const float4*)&ws[c * COUT_ + o0];
            float4 wb = *(const float4*)&ws[c * COUT_ + o0 + 4];
            float wr[8] = {wa.x, wa.y, wa.z, wa.w, wb.x, wb.y, wb.z, wb.w};
#pragma unroll
            for (int j = 0; j < 8; j++) {
                unsigned long long wp = pack2(wr[j]);
                ffma2(acc[2 * j    ], wp, cv.x);
                ffma2(acc[2 * j + 1], wp, cv.y);
            }
        }
    }

    // ---- epilogue: unpack, add bias, vectorized store ----
#pragma unroll
    for (int j = 0; j < 8; j++) {
        float bv = bias[o0 + j];
        float2 lo = unpack2(acc[2 * j]);
        float2 hi = unpack2(acc[2 * j + 1]);
        float4 r = make_float4(lo.x + bv, lo.y + bv, hi.x + bv, hi.y + bv);
        *(float4*)&out[(((b * COUT_) + o0 + j) * H_ + h) * W_ + px0] = r;
    }
}

extern "C" void kernel_launch(void* const* d_in, const int* in_sizes, int n_in,
                              void* d_out, int out_size) {
    const float* x      = (const float*)d_in[0];
    const float* offset = (const float*)d_in[1];
    const float* mask   = (const float*)d_in[2];
    const float* weight = (const float*)d_in[3];
    const float* bias   = (const float*)d_in[4];
    float* out = (float*)d_out;

    const int smem = (C_ * 128 + C_ * COUT_) * 4 + 128 * 16 * 2;  // 53248 B
    cudaFuncSetAttribute(dcn_kernel,
                         cudaFuncAttributeMaxDynamicSharedMemorySize, smem);

    wtrans_kernel<<<(K2_ * C_ * COUT_ + 255) / 256, 256>>>(weight);
    dcn_kernel<<<B_ * H_, 256, smem>>>(x, offset, mask, bias, out);
}

// round 10
// speedup vs baseline: 1.3502x; 1.3502x over previous
#include <cuda_runtime.h>
#include <cuda_bf16.h>
#include <cstdint>

#define B_    8
#define C_    64
#define H_    128
#define W_    128
#define HW_   (H_*W_)
#define COUT_ 64
#define K2_   9

// Pre-split, pre-swizzled bf16 weights: per tap k an 8KB tile [o=64 rows][64 c * 2B = 128B rows]
// byte(o,c) = o*128 + ((2c) ^ ((o&7)<<4))
__device__ __align__(16) uint16_t g_wB_hi[K2_ * 4096];
__device__ __align__(16) uint16_t g_wB_lo[K2_ * 4096];

// smem layout (bytes)
#define SM_WTS     0                        // float4[128] tap weights (2048)
#define SM_OFFS    2048                     // int4[128] tap offsets   (2048)
#define SM_COLS_HI 4096                     // [128 px][64 c] bf16, 16KB
#define SM_COLS_LO 20480                    // 16KB
#define SM_WB_HI   36864                    // [64 o][64 c] bf16, 8KB
#define SM_WB_LO   45056                    // 8KB
#define SM_TOTAL   53248

__device__ __forceinline__ uint32_t smem_u32(const void* p) {
    uint32_t a;
    asm("{ .reg .u64 t; cvta.to.shared.u64 t, %1; cvt.u32.u64 %0, t; }" : "=r"(a) : "l"(p));
    return a;
}
__device__ __forceinline__ void ldsm4(uint32_t* r, uint32_t a) {
    asm volatile("ldmatrix.sync.aligned.m8n8.x4.shared.b16 {%0,%1,%2,%3}, [%4];"
        : "=r"(r[0]), "=r"(r[1]), "=r"(r[2]), "=r"(r[3]) : "r"(a));
}
__device__ __forceinline__ void ldsm2(uint32_t* r, uint32_t a) {
    asm volatile("ldmatrix.sync.aligned.m8n8.x2.shared.b16 {%0,%1}, [%2];"
        : "=r"(r[0]), "=r"(r[1]) : "r"(a));
}
__device__ __forceinline__ void mma16816(float* d, const uint32_t* a, const uint32_t* b) {
    asm volatile("mma.sync.aligned.m16n8k16.row.col.f32.bf16.bf16.f32 "
        "{%0,%1,%2,%3}, {%4,%5,%6,%7}, {%8,%9}, {%0,%1,%2,%3};"
        : "+f"(d[0]), "+f"(d[1]), "+f"(d[2]), "+f"(d[3])
        : "r"(a[0]), "r"(a[1]), "r"(a[2]), "r"(a[3]), "r"(b[0]), "r"(b[1]));
}

// ---------------------------------------------------------------------------
// Pre-kernel: split weight[o][c][ky][kx] -> bf16 hi/lo swizzled tiles
// ---------------------------------------------------------------------------
__global__ void wprep_kernel(const float* __restrict__ w) {
    int e = blockIdx.x * 256 + threadIdx.x;      // e = (o*64 + c)*9 + k
    if (e >= K2_ * C_ * COUT_) return;
    int k = e % 9;
    int oc = e / 9;
    int c = oc % C_;
    int o = oc / C_;
    float v = w[e];
    __nv_bfloat16 hi = __float2bfloat16(v);
    __nv_bfloat16 lo = __float2bfloat16(v - __bfloat162float(hi));
    uint32_t byte = (uint32_t)o * 128 + (((uint32_t)(2 * c)) ^ ((uint32_t)(o & 7) << 4));
    g_wB_hi[k * 4096 + byte / 2] = __bfloat16_as_ushort(hi);
    g_wB_lo[k * 4096 + byte / 2] = __bfloat16_as_ushort(lo);
}

// ---------------------------------------------------------------------------
// Main kernel: one block = one (b, h) output row (M=128 px, N=64 Cout).
// Gather -> bf16 hi/lo cols smem -> ldmatrix + mma.sync (hh+hl+lh) -> stores.
// Warp w owns px rows [w*16, w*16+16); accumulators 16x64 f32 (32 regs).
// ---------------------------------------------------------------------------
__global__ void __launch_bounds__(256)
dcn_hmma_kernel(const float* __restrict__ x,
                const float* __restrict__ offset,
                const float* __restrict__ mask,
                const float* __restrict__ bias,
                float* __restrict__ out) {
    extern __shared__ char smc[];
    const uint32_t sbase = smem_u32(smc);

    const int t = threadIdx.x;
    const int wid = t >> 5;
    const int lane = t & 31;
    const int b = blockIdx.x >> 7;
    const int h = blockIdx.x & 127;
    const float* xb = x + b * C_ * HW_;

    // gather coords
    const int spx = t & 127;
    const int c0 = (t >> 7) * 32;
    const uint32_t rowbase = (uint32_t)spx * 128;
    const uint32_t xmask = (uint32_t)(spx & 7) << 4;

    // ldmatrix per-lane bases
    const uint32_t aswz = (uint32_t)(lane & 7) << 4;
    const uint32_t arow = (uint32_t)(wid * 16 + (lane & 15));
    const uint32_t aoffk = (uint32_t)(lane >> 4) * 16;           // 0 or 16
    const uint32_t aHi = sbase + SM_COLS_HI + arow * 128 + (((arow & 7) << 4) ? 0 : 0);
    const uint32_t aLo = sbase + SM_COLS_LO + arow * 128;
    const uint32_t aswzA = (uint32_t)(arow & 7) << 4;
    const uint32_t brow = (uint32_t)(lane & 7);
    const uint32_t boffk = (uint32_t)((lane >> 3) & 1) * 16;     // 0 or 16
    const uint32_t bHi = sbase + SM_WB_HI + brow * 128;
    const uint32_t bLo = sbase + SM_WB_LO + brow * 128;
    const uint32_t bswz = brow << 4;

    int4* offs = (int4*)(smc + SM_OFFS);
    float4* wts = (float4*)(smc + SM_WTS);

    float acc[8][4];
#pragma unroll
    for (int j = 0; j < 8; j++)
#pragma unroll
        for (int q = 0; q < 4; q++) acc[j][q] = 0.0f;

    for (int k = 0; k < 9; k++) {
        __syncthreads();   // previous tap's ldmatrix reads done before overwrite

        if (t < 128) {
            // ---- bilinear params for tap k, one pixel per thread ----
            const int w = t;
            const int ky = k / 3;
            const int kx = k - ky * 3;
            float dx = offset[(((b * 18) + 2 * k    ) * 128 + h) * 128 + w];
            float dy = offset[(((b * 18) + 2 * k + 1) * 128 + h) * 128 + w];
            float m  = mask  [(((b * 9)  + k        ) * 128 + h) * 128 + w];
            float py  = (float)(h - 1 + ky) + dy;
            float pxf = (float)(w - 1 + kx) + dx;
            float y0 = floorf(py), x0f = floorf(pxf);
            float ly = py - y0, lx = pxf - x0f;
            float hy = 1.0f - ly, hx = 1.0f - lx;
            int iy0 = (int)y0, ix0 = (int)x0f;
            int iy1 = iy0 + 1, ix1 = ix0 + 1;
            float vy0 = (iy0 >= 0 && iy0 < H_) ? 1.0f : 0.0f;
            float vy1 = (iy1 >= 0 && iy1 < H_) ? 1.0f : 0.0f;
            float vx0 = (ix0 >= 0 && ix0 < W_) ? 1.0f : 0.0f;
            float vx1 = (ix1 >= 0 && ix1 < W_) ? 1.0f : 0.0f;
            int iy0c = min(max(iy0, 0), H_ - 1);
            int iy1c = min(max(iy1, 0), H_ - 1);
            int ix0c = min(max(ix0, 0), W_ - 1);
            int ix1c = min(max(ix1, 0), W_ - 1);
            offs[w] = make_int4(iy0c * W_ + ix0c, iy0c * W_ + ix1c,
                                iy1c * W_ + ix0c, iy1c * W_ + ix1c);
            wts[w] = make_float4(hy * hx * m * vy0 * vx0,
                                 hy * lx * m * vy0 * vx1,
                                 ly * hx * m * vy1 * vx0,
                                 ly * lx * m * vy1 * vx1);
        } else {
            // ---- stage pre-swizzled bf16 weight tiles (8KB hi + 8KB lo) ----
            const uint4* srcH = (const uint4*)(g_wB_hi + (size_t)k * 4096);
            const uint4* srcL = (const uint4*)(g_wB_lo + (size_t)k * 4096);
            uint4* dstH = (uint4*)(smc + SM_WB_HI);
            uint4* dstL = (uint4*)(smc + SM_WB_LO);
            int i0 = t - 128;
#pragma unroll
            for (int j = 0; j < 4; j++) {
                dstH[i0 + j * 128] = __ldg(srcH + i0 + j * 128);
                dstL[i0 + j * 128] = __ldg(srcL + i0 + j * 128);
            }
        }
        __syncthreads();

        // ---- gather: 32 channels per thread, split to bf16 hi/lo, STS.128 ----
        {
            int4 o4 = offs[spx];
            float4 w4 = wts[spx];
            const float* pc = xb + c0 * HW_;
#pragma unroll
            for (int g = 0; g < 4; g++) {            // 4 groups of 8 channels
                uint32_t hb[4], lb[4];
#pragma unroll
                for (int p = 0; p < 4; p++) {        // 2 channels per iter
                    float v0 = w4.x * __ldg(pc + o4.x) + w4.y * __ldg(pc + o4.y)
                             + w4.z * __ldg(pc + o4.z) + w4.w * __ldg(pc + o4.w);
                    pc += HW_;
                    float v1 = w4.x * __ldg(pc + o4.x) + w4.y * __ldg(pc + o4.y)
                             + w4.z * __ldg(pc + o4.z) + w4.w * __ldg(pc + o4.w);
                    pc += HW_;
                    uint32_t hp;
                    asm("cvt.rn.bf16x2.f32 %0, %1, %2;" : "=r"(hp) : "f"(v1), "f"(v0));
                    float r0 = v0 - __uint_as_float(hp << 16);
                    float r1 = v1 - __uint_as_float(hp & 0xFFFF0000u);
                    uint32_t lp;
                    asm("cvt.rn.bf16x2.f32 %0, %1, %2;" : "=r"(lp) : "f"(r1), "f"(r0));
                    hb[p] = hp;
                    lb[p] = lp;
                }
                uint32_t off = rowbase + (((uint32_t)(c0 * 2 + g * 16)) ^ xmask);
                *(uint4*)(smc + SM_COLS_HI + off) = make_uint4(hb[0], hb[1], hb[2], hb[3]);
                *(uint4*)(smc + SM_COLS_LO + off) = make_uint4(lb[0], lb[1], lb[2], lb[3]);
            }
        }
        __syncthreads();

        // ---- warp GEMM: 4 K-steps x 8 n-tiles x 3 products ----
#pragma unroll
        for (int s = 0; s < 4; s++) {
            uint32_t ka = ((uint32_t)(s * 32) + aoffk) ^ aswzA;
            uint32_t ah[4], al[4];
            ldsm4(ah, aHi + ka);
            ldsm4(al, aLo + ka);
            uint32_t kb = ((uint32_t)(s * 32) + boffk) ^ bswz;
#pragma unroll
            for (int j = 0; j < 8; j++) {
                uint32_t bh[2], bl[2];
                ldsm2(bh, bHi + (uint32_t)j * 1024 + kb);
                ldsm2(bl, bLo + (uint32_t)j * 1024 + kb);
                mma16816(acc[j], ah, bh);
                mma16816(acc[j], ah, bl);
                mma16816(acc[j], al, bh);
            }
        }
    }

    // ---- epilogue: add bias, store from accumulators ----
    const int pxb = wid * 16 + (lane >> 2);
#pragma unroll
    for (int j = 0; j < 8; j++) {
        int o = j * 8 + (lane & 3) * 2;
        float bv0 = __ldg(bias + o);
        float bv1 = __ldg(bias + o + 1);
        float* op0 = out + (((size_t)b * COUT_ + o) * H_ + h) * W_;
        float* op1 = op0 + HW_;
        op0[pxb]     = acc[j][0] + bv0;
        op1[pxb]     = acc[j][1] + bv1;
        op0[pxb + 8] = acc[j][2] + bv0;
        op1[pxb + 8] = acc[j][3] + bv1;
    }
}

extern "C" void kernel_launch(void* const* d_in, const int* in_sizes, int n_in,
                              void* d_out, int out_size) {
    const float* x      = (const float*)d_in[0];
    const float* offset = (const float*)d_in[1];
    const float* mask   = (const float*)d_in[2];
    const float* weight = (const float*)d_in[3];
    const float* bias   = (const float*)d_in[4];
    float* out = (float*)d_out;

    cudaFuncSetAttribute(dcn_hmma_kernel,
                         cudaFuncAttributeMaxDynamicSharedMemorySize, SM_TOTAL);

    wprep_kernel<<<(K2_ * C_ * COUT_ + 255) / 256, 256>>>(weight);
    dcn_hmma_kernel<<<B_ * H_, 256, SM_TOTAL>>>(x, offset, mask, bias, out);
}